// round 5
// baseline (speedup 1.0000x reference)
#include <cuda_runtime.h>
#include <cuda_bf16.h>
#include <cstdint>
#include <math.h>

#define BB 16
#define CC 512
#define SS 1024
#define PER_B (CC*SS)

typedef __nv_bfloat16 bf16;

// ---------------- scratch (__device__ globals; no allocs) ----------------
__device__ float g_psum[BB*64], g_psq[BB*64], g_stats[BB*2];
__device__ unsigned g_ctr;
__device__ bf16  g_h2 [(size_t)BB*SS*1024];   // norm'd [B*S, hi|lo]  (A-side, fold 1024)
__device__ bf16  g_w1 [1536*1024];            // qkv_w  [hi|lo]      (B-side, fold 512)
__device__ bf16  g_w2 [512*1024];             // proj_w [hi|lo]      (B-side, fold 512)
__device__ bf16  g_q2 [(size_t)BB*SS*1024];   // Q [hi|lo] (A-side)
__device__ bf16  g_k2 [(size_t)BB*SS*1024];   // K [hi|lo] (B-side)
__device__ bf16  g_v2 [(size_t)BB*CC*2048];   // V transposed [B,C, hi|lo over S] (B-side)
__device__ bf16  g_p2 [(size_t)BB*SS*2048];   // probs [B*S, hi|lo] (A-side, fold 2048)
__device__ bf16  g_ao2[(size_t)BB*SS*1024];   // attn out [hi|lo] (A-side)
__device__ float g_sc [(size_t)BB*SS*SS];     // scores fp32

// ---------------- helpers ----------------
__device__ __forceinline__ uint32_t smem_u32(const void* p) {
    uint32_t a;
    asm("{ .reg .u64 t; cvta.to.shared.u64 t, %1; cvt.u32.u64 %0, t; }" : "=r"(a) : "l"(p));
    return a;
}
#define CP_ASYNC16(dst, src) \
    asm volatile("cp.async.cg.shared.global [%0], [%1], 16;" :: "r"(dst), "l"(src) : "memory")
#define CP_COMMIT() asm volatile("cp.async.commit_group;" ::: "memory")
#define CP_WAIT0()  asm volatile("cp.async.wait_group 0;" ::: "memory")
#define CP_WAIT1()  asm volatile("cp.async.wait_group 1;" ::: "memory")
#define CP_WAIT2()  asm volatile("cp.async.wait_group 2;" ::: "memory")
#define LDM_X4(r0,r1,r2,r3,addr) \
    asm volatile("ldmatrix.sync.aligned.m8n8.x4.shared.b16 {%0,%1,%2,%3}, [%4];" \
        : "=r"(r0),"=r"(r1),"=r"(r2),"=r"(r3) : "r"(addr))
#define MMA16816(d, a, b0, b1) \
    asm volatile("mma.sync.aligned.m16n8k16.row.col.f32.bf16.bf16.f32 " \
        "{%0,%1,%2,%3}, {%4,%5,%6,%7}, {%8,%9}, {%0,%1,%2,%3};" \
        : "+f"((d)[0]), "+f"((d)[1]), "+f"((d)[2]), "+f"((d)[3]) \
        : "r"((a)[0]), "r"((a)[1]), "r"((a)[2]), "r"((a)[3]), "r"(b0), "r"(b1))

__device__ __forceinline__ void split2(float v, bf16& hi, bf16& lo) {
    hi = __float2bfloat16(v);
    lo = __float2bfloat16(v - __bfloat162float(hi));
}

// ---------------- fused weight split (both weights, stored [hi|lo]) ----------------
__global__ void wsplit_all(const float* __restrict__ w1s, const float* __restrict__ w2s) {
    int i = blockIdx.x * 256 + threadIdx.x;
    if (i < 2048*512) {
        int r = i >> 9, c = i & 511;
        float v; bf16* row;
        if (r < 1536) { v = w1s[i]; row = g_w1 + (size_t)r * 1024; }
        else          { v = w2s[i - 1536*512]; row = g_w2 + (size_t)(r - 1536) * 1024; }
        bf16 hi, lo; split2(v, hi, lo);
        row[c] = hi; row[512 + c] = lo;
    }
}

// ---------------- fused GroupNorm stats (partial + last-block finalize) ----------------
__global__ void gn_stats(const float* __restrict__ x) {
    int b = blockIdx.y, chunk = blockIdx.x, t = threadIdx.x;
    const float* p = x + (size_t)b*PER_B + (size_t)chunk*8192;
    float s = 0.f, q = 0.f;
#pragma unroll
    for (int i = 0; i < 32; i++) { float v = p[t + i*256]; s += v; q += v*v; }
    __shared__ float ss_[8], sq_[8];
    for (int o = 16; o > 0; o >>= 1) {
        s += __shfl_down_sync(0xffffffffu, s, o);
        q += __shfl_down_sync(0xffffffffu, q, o);
    }
    if ((t & 31) == 0) { ss_[t >> 5] = s; sq_[t >> 5] = q; }
    __syncthreads();
    __shared__ int isLast;
    if (t == 0) {
        float S2 = 0.f, Q2 = 0.f;
#pragma unroll
        for (int i = 0; i < 8; i++) { S2 += ss_[i]; Q2 += sq_[i]; }
        g_psum[b*64 + chunk] = S2; g_psq[b*64 + chunk] = Q2;
        __threadfence();
        unsigned v = atomicAdd(&g_ctr, 1u);
        isLast = (v == 64u*BB - 1u);
    }
    __syncthreads();
    if (isLast) {
        if (t < BB) {
            float s2 = 0.f, q2 = 0.f;
            for (int i = 0; i < 64; i++) { s2 += g_psum[t*64+i]; q2 += g_psq[t*64+i]; }
            float mean = s2 * (1.f/(float)PER_B);
            float var  = q2 * (1.f/(float)PER_B) - mean*mean;
            g_stats[2*t] = mean; g_stats[2*t+1] = rsqrtf(var + 1e-5f);
        }
        if (t == 0) g_ctr = 0u;
    }
}

// ---------------- normalize + transpose + split -> g_h2 [B*S, hi|lo] ----------------
__global__ void norm_split(const float* __restrict__ x,
                           const float* __restrict__ gw,
                           const float* __restrict__ gb) {
    __shared__ float tile[32][33];
    int b = blockIdx.z;
    int s0 = blockIdx.x * 32, c0 = blockIdx.y * 32;
    int tx = threadIdx.x, ty = threadIdx.y;
    const float* xp = x + (size_t)b * PER_B;
#pragma unroll
    for (int i = 0; i < 4; i++) {
        int c = c0 + ty + i*8;
        tile[ty + i*8][tx] = xp[(size_t)c*SS + s0 + tx];
    }
    __syncthreads();
    float mean = g_stats[2*b], inv = g_stats[2*b+1];
    int c = c0 + tx;
    float w  = gw[c] * inv;
    float bias = gb[c] - mean * w;
#pragma unroll
    for (int i = 0; i < 4; i++) {
        int s = s0 + ty + i*8;
        float v = tile[tx][ty + i*8] * w + bias;
        bf16 hi, lo; split2(v, hi, lo);
        bf16* row = g_h2 + ((size_t)b*SS + s) * 1024;
        row[c] = hi; row[512 + c] = lo;
    }
}

// ---------------- HMMA GEMM: 128x256 CTA, 8 warps (64x64 each), BK=32, 4-stage ----------------
// NT logical: out[m,n] = sum_k A[m,k_effA]*B[n,k_effB], k_eff = k>=thresh ? k-thresh : k
// EPI: 0 = QKV split-out, 1 = scores*scale, 2 = AV split-out, 3 = proj+bias+resid (NCHW)
#define STAGE_BYTES 30720        // A 128x80 (10240) + B 256x80 (20480)
#define DYN_SMEM 135168          // max(4*30720, 128*264*4)

__device__ __forceinline__ void prefetch_tile(char* smem, int stage,
    const bf16* __restrict__ A, int lda, const bf16* __restrict__ B, int ldb,
    int m0, int n0, int kA, int kB, int tid)
{
    char* as = smem + stage*STAGE_BYTES;
    char* bs = as + 10240;
    int ar = tid >> 1, ah = tid & 1;
    const bf16* ag = A + (size_t)(m0 + ar)*lda + kA + ah*16;
    uint32_t asw = smem_u32(as + ar*80 + ah*32);
    CP_ASYNC16(asw,      (const void*)ag);
    CP_ASYNC16(asw + 16, (const void*)(ag + 8));
    const bf16* bg = B + (size_t)(n0 + tid)*ldb + kB;
    uint32_t bsw = smem_u32(bs + tid*80);
    CP_ASYNC16(bsw,      (const void*)bg);
    CP_ASYNC16(bsw + 16, (const void*)(bg + 8));
    CP_ASYNC16(bsw + 32, (const void*)(bg + 16));
    CP_ASYNC16(bsw + 48, (const void*)(bg + 24));
}

template<int EPI>
__global__ __launch_bounds__(256, 1)
void mm_gemm(const bf16* __restrict__ A, int lda, long long sA, int thA,
             const bf16* __restrict__ B, int ldb, long long sB, int thB,
             float* __restrict__ Out,
             const float* __restrict__ bias,
             const float* __restrict__ resid,
             float scale, int K)
{
    extern __shared__ char smem[];
    int tid = threadIdx.x, lane = tid & 31, wid = tid >> 5;
    int wm = wid >> 2, wn = wid & 3;          // 2 x 4 warp grid, 64x64 tiles
    int z = blockIdx.z;
    int m0 = blockIdx.y * 128, n0 = blockIdx.x * 256;
    A += (size_t)z * sA;
    B += (size_t)z * sB;

    float acc[4][8][4];
#pragma unroll
    for (int i = 0; i < 4; i++)
#pragma unroll
        for (int j = 0; j < 8; j++)
#pragma unroll
            for (int r = 0; r < 4; r++) acc[i][j][r] = 0.f;

    uint32_t a_off = (uint32_t)((wm*64 + (lane & 15)) * 80 + (lane >> 4) * 16);
    uint32_t b_off = (uint32_t)((wn*64 + (lane & 7) + ((lane >> 4) << 3)) * 80
                                + ((lane >> 3) & 1) * 16);
    uint32_t smem_base = smem_u32(smem);

    int nch = K >> 5;
#pragma unroll
    for (int p = 0; p < 3; p++) {
        if (p < nch) {
            int k0 = p * 32;
            prefetch_tile(smem, p, A, lda, B, ldb, m0, n0,
                          (k0 >= thA) ? k0 - thA : k0, (k0 >= thB) ? k0 - thB : k0, tid);
            CP_COMMIT();
        }
    }

    int st = 0;
    for (int c = 0; c < nch; c++) {
        int rem = nch - 1 - c;
        if (rem >= 2) CP_WAIT2(); else if (rem == 1) CP_WAIT1(); else CP_WAIT0();
        __syncthreads();
        if (c + 3 < nch) {
            int k0 = (c + 3) * 32;
            prefetch_tile(smem, (st + 3) & 3, A, lda, B, ldb, m0, n0,
                          (k0 >= thA) ? k0 - thA : k0, (k0 >= thB) ? k0 - thB : k0, tid);
            CP_COMMIT();
        }

        uint32_t as_b = smem_base + st*STAGE_BYTES + a_off;
        uint32_t bs_b = smem_base + st*STAGE_BYTES + 10240 + b_off;
#pragma unroll
        for (int ks = 0; ks < 2; ks++) {
            uint32_t a[4][4], b[4][4];
#pragma unroll
            for (int mf = 0; mf < 4; mf++)
                LDM_X4(a[mf][0], a[mf][1], a[mf][2], a[mf][3], as_b + mf*1280 + ks*32);
#pragma unroll
            for (int nf2 = 0; nf2 < 4; nf2++)
                LDM_X4(b[nf2][0], b[nf2][1], b[nf2][2], b[nf2][3], bs_b + nf2*1280 + ks*32);
#pragma unroll
            for (int mf = 0; mf < 4; mf++)
#pragma unroll
                for (int nf = 0; nf < 8; nf++)
                    MMA16816(acc[mf][nf], a[mf], b[nf>>1][(nf&1)*2], b[nf>>1][(nf&1)*2+1]);
        }
        st = (st + 1) & 3;
    }
    __syncthreads();

    // stage accumulators to smem fp32 [128][264]
    float* tile = (float*)smem;
    {
        int r = lane >> 2, cp = (lane & 3) * 2;
#pragma unroll
        for (int mf = 0; mf < 4; mf++)
#pragma unroll
            for (int nf = 0; nf < 8; nf++) {
                int rr = wm*64 + mf*16 + r, cc = wn*64 + nf*8 + cp;
                tile[rr*264 + cc]       = acc[mf][nf][0];
                tile[rr*264 + cc + 1]   = acc[mf][nf][1];
                tile[(rr+8)*264 + cc]   = acc[mf][nf][2];
                tile[(rr+8)*264 + cc+1] = acc[mf][nf][3];
            }
    }
    __syncthreads();

    if constexpr (EPI == 0) {
        if (n0 < 512) {              // Q (A-side [hi|lo])
            for (int idx = tid; idx < 32768; idx += 256) {
                int r = idx >> 8, cc = idx & 255;
                float v = tile[r*264 + cc] + bias[n0 + cc];
                bf16 hi, lo; split2(v, hi, lo);
                bf16* row = g_q2 + (size_t)(m0 + r) * 1024;
                int n = n0 + cc;
                row[n] = hi; row[512 + n] = lo;
            }
        } else if (n0 < 1024) {      // K (B-side [hi|lo])
            for (int idx = tid; idx < 32768; idx += 256) {
                int r = idx >> 8, cc = idx & 255;
                float v = tile[r*264 + cc] + bias[n0 + cc];
                bf16 hi, lo; split2(v, hi, lo);
                bf16* row = g_k2 + (size_t)(m0 + r) * 1024;
                int n = n0 + cc - 512;
                row[n] = hi; row[512 + n] = lo;
            }
        } else {                     // V -> transposed [B,C, hi|lo over S]
            for (int idx = tid; idx < 32768; idx += 256) {
                int rt = idx & 127, ct = idx >> 7;
                float v = tile[rt*264 + ct] + bias[n0 + ct];
                bf16 hi, lo; split2(v, hi, lo);
                int m = m0 + rt, b = m >> 10, s = m & 1023;
                int cg = n0 + ct - 1024;
                bf16* row = g_v2 + ((size_t)b*512 + cg) * 2048;
                row[s] = hi; row[1024 + s] = lo;
            }
        }
    } else if constexpr (EPI == 1) { // scores fp32
        float* op = Out + (size_t)z * SS * SS;
        for (int idx = tid; idx < 32768; idx += 256) {
            int r = idx >> 8, cc = idx & 255;
            op[(size_t)(m0 + r) * SS + n0 + cc] = tile[r*264 + cc] * scale;
        }
    } else if constexpr (EPI == 2) { // AV out (A-side [hi|lo])
        for (int idx = tid; idx < 32768; idx += 256) {
            int r = idx >> 8, cc = idx & 255;
            float v = tile[r*264 + cc];
            bf16 hi, lo; split2(v, hi, lo);
            bf16* row = g_ao2 + ((size_t)z * SS + m0 + r) * 1024;
            int n = n0 + cc;
            row[n] = hi; row[512 + n] = lo;
        }
    } else {                         // proj: +bias +residual, NCHW transposed write
        for (int idx = tid; idx < 32768; idx += 256) {
            int rt = idx & 127, ct = idx >> 7;
            int m = m0 + rt, b = m >> 10, s = m & 1023;
            int n = n0 + ct;
            size_t oidx = ((size_t)b * 512 + n) * 1024 + s;
            Out[oidx] = tile[rt*264 + ct] + bias[n] + resid[oidx];
        }
    }
}

// ---------------- softmax over 1024-wide rows, [hi|lo] output ----------------
__global__ void softmax_rows(const float* __restrict__ sc) {
    const float* row = sc + (size_t)blockIdx.x * SS;
    bf16* orow = g_p2 + (size_t)blockIdx.x * 2048;
    int t = threadIdx.x;
    float v[4];
#pragma unroll
    for (int i = 0; i < 4; i++) v[i] = row[t + i*256];
    float m = fmaxf(fmaxf(v[0], v[1]), fmaxf(v[2], v[3]));
    __shared__ float red[8];
    for (int o = 16; o > 0; o >>= 1) m = fmaxf(m, __shfl_xor_sync(0xffffffffu, m, o));
    if ((t & 31) == 0) red[t >> 5] = m;
    __syncthreads();
    float mm = fmaxf(fmaxf(fmaxf(red[0], red[1]), fmaxf(red[2], red[3])),
                     fmaxf(fmaxf(red[4], red[5]), fmaxf(red[6], red[7])));
    float s = 0.f;
#pragma unroll
    for (int i = 0; i < 4; i++) { v[i] = __expf(v[i] - mm); s += v[i]; }
    for (int o = 16; o > 0; o >>= 1) s += __shfl_xor_sync(0xffffffffu, s, o);
    __syncthreads();
    if ((t & 31) == 0) red[t >> 5] = s;
    __syncthreads();
    float tot = ((red[0]+red[1]) + (red[2]+red[3])) + ((red[4]+red[5]) + (red[6]+red[7]));
    float invs = 1.f / tot;
#pragma unroll
    for (int i = 0; i < 4; i++) {
        float p = v[i] * invs;
        bf16 hi, lo; split2(p, hi, lo);
        int k = t + i*256;
        orow[k] = hi; orow[1024 + k] = lo;
    }
}

// ---------------- launch ----------------
extern "C" void kernel_launch(void* const* d_in, const int* in_sizes, int n_in,
                              void* d_out, int out_size) {
    const float* x      = (const float*)d_in[0];
    const float* gn_w   = (const float*)d_in[1];
    const float* gn_b   = (const float*)d_in[2];
    const float* qkv_w  = (const float*)d_in[3];
    const float* qkv_b  = (const float*)d_in[4];
    const float* proj_w = (const float*)d_in[5];
    const float* proj_b = (const float*)d_in[6];
    float* out = (float*)d_out;

    cudaFuncSetAttribute(mm_gemm<0>, cudaFuncAttributeMaxDynamicSharedMemorySize, DYN_SMEM);
    cudaFuncSetAttribute(mm_gemm<1>, cudaFuncAttributeMaxDynamicSharedMemorySize, DYN_SMEM);
    cudaFuncSetAttribute(mm_gemm<2>, cudaFuncAttributeMaxDynamicSharedMemorySize, DYN_SMEM);
    cudaFuncSetAttribute(mm_gemm<3>, cudaFuncAttributeMaxDynamicSharedMemorySize, DYN_SMEM);

    bf16 *h2, *w1, *w2, *q2, *k2, *v2, *p2, *ao2; float* sc;
    cudaGetSymbolAddress((void**)&h2,  g_h2);
    cudaGetSymbolAddress((void**)&w1,  g_w1);
    cudaGetSymbolAddress((void**)&w2,  g_w2);
    cudaGetSymbolAddress((void**)&q2,  g_q2);
    cudaGetSymbolAddress((void**)&k2,  g_k2);
    cudaGetSymbolAddress((void**)&v2,  g_v2);
    cudaGetSymbolAddress((void**)&p2,  g_p2);
    cudaGetSymbolAddress((void**)&ao2, g_ao2);
    cudaGetSymbolAddress((void**)&sc,  g_sc);

    // 1. fused weight splits
    wsplit_all<<<(2048*512 + 255)/256, 256>>>(qkv_w, proj_w);

    // 2. fused GroupNorm stats
    gn_stats<<<dim3(64, BB), 256>>>(x);

    // 3. normalize + transpose + split
    norm_split<<<dim3(SS/32, CC/32, BB), dim3(32, 8)>>>(x, gn_w, gn_b);

    // 4. QKV GEMM: M=16384, N=1536, K=1536 (logical)  <-- profiled slot
    mm_gemm<0><<<dim3(6, 128, 1), 256, DYN_SMEM>>>(
        h2, 1024, 0LL, 1024, w1, 1024, 0LL, 512,
        nullptr, qkv_b, nullptr, 1.f, 1536);

    // 5. scores = scale * Q K^T, batched: M=N=1024, K=1536 (logical)
    mm_gemm<1><<<dim3(4, 8, BB), 256, DYN_SMEM>>>(
        q2, 1024, 1024LL*1024, 1024, k2, 1024, 1024LL*1024, 512, sc,
        nullptr, nullptr, 0.044194173824159216f, 1536);

    // 6. softmax + split
    softmax_rows<<<BB*SS, 256>>>(sc);

    // 7. attn @ V: M=1024, N=512, K=3072 (logical), batched
    mm_gemm<2><<<dim3(2, 8, BB), 256, DYN_SMEM>>>(
        p2, 2048, 1024LL*2048, 2048, v2, 2048, 512LL*2048, 1024, nullptr,
        nullptr, nullptr, 1.f, 3072);

    // 8. proj + bias + residual -> NCHW out: M=16384, N=512, K=1536 (logical)
    mm_gemm<3><<<dim3(2, 128, 1), 256, DYN_SMEM>>>(
        ao2, 1024, 0LL, 1024, w2, 1024, 0LL, 512, out, proj_b, x, 1.f, 1536);
}

// round 7
// speedup vs baseline: 1.0706x; 1.0706x over previous
#include <cuda_runtime.h>
#include <cuda_bf16.h>
#include <cstdint>
#include <math.h>

#define BB 16
#define CC 512
#define SS 1024
#define PER_B (CC*SS)

typedef __nv_bfloat16 bf16;

// ---------------- scratch (__device__ globals; no allocs) ----------------
__device__ float g_psum[BB*64], g_psq[BB*64], g_stats[BB*2];
__device__ unsigned g_ctr;
__device__ bf16  g_h2 [(size_t)BB*SS*1024];   // norm'd [B*S, hi|lo]  (A-side, fold 1024)
__device__ bf16  g_w1 [1536*1024];            // qkv_w  [hi|lo]      (B-side, fold 512)
__device__ bf16  g_w2 [512*1024];             // proj_w [hi|lo]      (B-side, fold 512)
__device__ bf16  g_q2 [(size_t)BB*SS*1024];   // Q [hi|lo] (A-side)
__device__ bf16  g_k2 [(size_t)BB*SS*1024];   // K [hi|lo] (B-side)
__device__ bf16  g_v2 [(size_t)BB*CC*2048];   // V transposed [B,C, hi|lo over S] (B-side)
__device__ bf16  g_p2 [(size_t)BB*SS*2048];   // probs [B*S, hi|lo] (A-side, fold 2048)
__device__ bf16  g_ao2[(size_t)BB*SS*1024];   // attn out [hi|lo] (A-side)
__device__ float g_sc [(size_t)BB*SS*SS];     // scores fp32

// ---------------- helpers ----------------
__device__ __forceinline__ uint32_t smem_u32(const void* p) {
    uint32_t a;
    asm("{ .reg .u64 t; cvta.to.shared.u64 t, %1; cvt.u32.u64 %0, t; }" : "=r"(a) : "l"(p));
    return a;
}
#define CP_ASYNC16(dst, src) \
    asm volatile("cp.async.cg.shared.global [%0], [%1], 16;" :: "r"(dst), "l"(src) : "memory")
#define CP_COMMIT() asm volatile("cp.async.commit_group;" ::: "memory")
#define CP_WAIT0()  asm volatile("cp.async.wait_group 0;" ::: "memory")
#define LDM_X4(r0,r1,r2,r3,addr) \
    asm volatile("ldmatrix.sync.aligned.m8n8.x4.shared.b16 {%0,%1,%2,%3}, [%4];" \
        : "=r"(r0),"=r"(r1),"=r"(r2),"=r"(r3) : "r"(addr))
#define MMA16816(d, a, b0, b1) \
    asm volatile("mma.sync.aligned.m16n8k16.row.col.f32.bf16.bf16.f32 " \
        "{%0,%1,%2,%3}, {%4,%5,%6,%7}, {%8,%9}, {%0,%1,%2,%3};" \
        : "+f"((d)[0]), "+f"((d)[1]), "+f"((d)[2]), "+f"((d)[3]) \
        : "r"((a)[0]), "r"((a)[1]), "r"((a)[2]), "r"((a)[3]), "r"(b0), "r"(b1))

__device__ __forceinline__ void split2(float v, bf16& hi, bf16& lo) {
    hi = __float2bfloat16(v);
    lo = __float2bfloat16(v - __bfloat162float(hi));
}

// ---------------- fused weight split (both weights, stored [hi|lo]) ----------------
__global__ void wsplit_all(const float* __restrict__ w1s, const float* __restrict__ w2s) {
    int i = blockIdx.x * 256 + threadIdx.x;
    if (i < 2048*512) {
        int r = i >> 9, c = i & 511;
        float v; bf16* row;
        if (r < 1536) { v = w1s[i]; row = g_w1 + (size_t)r * 1024; }
        else          { v = w2s[i - 1536*512]; row = g_w2 + (size_t)(r - 1536) * 1024; }
        bf16 hi, lo; split2(v, hi, lo);
        row[c] = hi; row[512 + c] = lo;
    }
}

// ---------------- fused GroupNorm stats (partial + last-block finalize) ----------------
__global__ void gn_stats(const float* __restrict__ x) {
    int b = blockIdx.y, chunk = blockIdx.x, t = threadIdx.x;
    const float* p = x + (size_t)b*PER_B + (size_t)chunk*8192;
    float s = 0.f, q = 0.f;
#pragma unroll
    for (int i = 0; i < 32; i++) { float v = p[t + i*256]; s += v; q += v*v; }
    __shared__ float ss_[8], sq_[8];
    for (int o = 16; o > 0; o >>= 1) {
        s += __shfl_down_sync(0xffffffffu, s, o);
        q += __shfl_down_sync(0xffffffffu, q, o);
    }
    if ((t & 31) == 0) { ss_[t >> 5] = s; sq_[t >> 5] = q; }
    __syncthreads();
    __shared__ int isLast;
    if (t == 0) {
        float S2 = 0.f, Q2 = 0.f;
#pragma unroll
        for (int i = 0; i < 8; i++) { S2 += ss_[i]; Q2 += sq_[i]; }
        g_psum[b*64 + chunk] = S2; g_psq[b*64 + chunk] = Q2;
        __threadfence();
        unsigned v = atomicAdd(&g_ctr, 1u);
        isLast = (v == 64u*BB - 1u);
    }
    __syncthreads();
    if (isLast) {
        if (t < BB) {
            float s2 = 0.f, q2 = 0.f;
            for (int i = 0; i < 64; i++) { s2 += g_psum[t*64+i]; q2 += g_psq[t*64+i]; }
            float mean = s2 * (1.f/(float)PER_B);
            float var  = q2 * (1.f/(float)PER_B) - mean*mean;
            g_stats[2*t] = mean; g_stats[2*t+1] = rsqrtf(var + 1e-5f);
        }
        if (t == 0) g_ctr = 0u;
    }
}

// ---------------- normalize + transpose + split -> g_h2 [B*S, hi|lo] ----------------
__global__ void norm_split(const float* __restrict__ x,
                           const float* __restrict__ gw,
                           const float* __restrict__ gb) {
    __shared__ float tile[32][33];
    int b = blockIdx.z;
    int s0 = blockIdx.x * 32, c0 = blockIdx.y * 32;
    int tx = threadIdx.x, ty = threadIdx.y;
    const float* xp = x + (size_t)b * PER_B;
#pragma unroll
    for (int i = 0; i < 4; i++) {
        int c = c0 + ty + i*8;
        tile[ty + i*8][tx] = xp[(size_t)c*SS + s0 + tx];
    }
    __syncthreads();
    float mean = g_stats[2*b], inv = g_stats[2*b+1];
    int c = c0 + tx;
    float w  = gw[c] * inv;
    float bias = gb[c] - mean * w;
#pragma unroll
    for (int i = 0; i < 4; i++) {
        int s = s0 + ty + i*8;
        float v = tile[tx][ty + i*8] * w + bias;
        bf16 hi, lo; split2(v, hi, lo);
        bf16* row = g_h2 + ((size_t)b*SS + s) * 1024;
        row[c] = hi; row[512 + c] = lo;
    }
}

// ---------------- HMMA GEMM: 128x128 CTA, 8 warps (32x64 each), BK=64, 2-stage ----------------
// NT logical: out[m,n] = sum_k A[m,k_effA]*B[n,k_effB], k_eff = k>=thresh ? k-thresh : k
// EPI: 0 = QKV split-out, 1 = scores*scale, 2 = AV split-out, 3 = proj+bias+resid (NCHW)
#define STAGE_BYTES 36864        // A 128x144 (18432) + B 128x144 (18432)
#define DYN_SMEM 73728           // max(2*36864, 128*132*4=67584)

__device__ __forceinline__ void prefetch_tile(char* smem, int stage,
    const bf16* __restrict__ A, int lda, const bf16* __restrict__ B, int ldb,
    int m0, int n0, int kA, int kB, int tid)
{
    char* as = smem + stage*STAGE_BYTES;
    char* bs = as + 18432;
#pragma unroll
    for (int i = 0; i < 4; i++) {
        int s = tid + i*256;              // 0..1023
        int row = s >> 3, c16 = s & 7;    // 8 x 16B segs per 128B of row data
        CP_ASYNC16(smem_u32(as + row*144 + c16*16),
                   (const void*)(A + (size_t)(m0+row)*lda + kA + c16*8));
        CP_ASYNC16(smem_u32(bs + row*144 + c16*16),
                   (const void*)(B + (size_t)(n0+row)*ldb + kB + c16*8));
    }
}

template<int EPI>
__global__ __launch_bounds__(256, 2)
void mm_gemm(const bf16* __restrict__ A, int lda, long long sA, int thA,
             const bf16* __restrict__ B, int ldb, long long sB, int thB,
             float* __restrict__ Out,
             const float* __restrict__ bias,
             const float* __restrict__ resid,
             float scale, int K)
{
    extern __shared__ char smem[];
    int tid = threadIdx.x, lane = tid & 31, wid = tid >> 5;
    int wm = wid >> 1, wn = wid & 1;          // 4 x 2 warp grid, 32x64 tiles
    int z = blockIdx.z;
    int m0 = blockIdx.y * 128, n0 = blockIdx.x * 128;
    A += (size_t)z * sA;
    B += (size_t)z * sB;

    float acc[2][8][4];
#pragma unroll
    for (int i = 0; i < 2; i++)
#pragma unroll
        for (int j = 0; j < 8; j++)
#pragma unroll
            for (int r = 0; r < 4; r++) acc[i][j][r] = 0.f;

    uint32_t a_off = (uint32_t)((wm*32 + (lane & 15)) * 144 + (lane >> 4) * 16);
    uint32_t b_off = (uint32_t)((wn*64 + (lane & 7) + ((lane >> 4) << 3)) * 144
                                + ((lane >> 3) & 1) * 16);
    uint32_t smem_base = smem_u32(smem);

    int nch = K >> 6;
    prefetch_tile(smem, 0, A, lda, B, ldb, m0, n0, 0, 0, tid);
    CP_COMMIT();

    int st = 0;
    for (int c = 0; c < nch; c++) {
        CP_WAIT0();
        __syncthreads();
        if (c + 1 < nch) {
            int k0 = (c + 1) * 64;
            prefetch_tile(smem, st ^ 1, A, lda, B, ldb, m0, n0,
                          (k0 >= thA) ? k0 - thA : k0, (k0 >= thB) ? k0 - thB : k0, tid);
            CP_COMMIT();
        }

        uint32_t as_b = smem_base + st*STAGE_BYTES + a_off;
        uint32_t bs_b = smem_base + st*STAGE_BYTES + 18432 + b_off;
#pragma unroll
        for (int ks = 0; ks < 4; ks++) {
            uint32_t a[2][4], b[4][4];
#pragma unroll
            for (int mf = 0; mf < 2; mf++)
                LDM_X4(a[mf][0], a[mf][1], a[mf][2], a[mf][3], as_b + mf*2304 + ks*32);
#pragma unroll
            for (int nf2 = 0; nf2 < 4; nf2++)
                LDM_X4(b[nf2][0], b[nf2][1], b[nf2][2], b[nf2][3], bs_b + nf2*2304 + ks*32);
#pragma unroll
            for (int mf = 0; mf < 2; mf++)
#pragma unroll
                for (int nf = 0; nf < 8; nf++)
                    MMA16816(acc[mf][nf], a[mf], b[nf>>1][(nf&1)*2], b[nf>>1][(nf&1)*2+1]);
        }
        st ^= 1;
    }
    __syncthreads();

    // stage accumulators to smem fp32 [128][132]
    float* tile = (float*)smem;
    {
        int r = lane >> 2, cp = (lane & 3) * 2;
#pragma unroll
        for (int mf = 0; mf < 2; mf++)
#pragma unroll
            for (int nf = 0; nf < 8; nf++) {
                int rr = wm*32 + mf*16 + r, cc = wn*64 + nf*8 + cp;
                tile[rr*132 + cc]       = acc[mf][nf][0];
                tile[rr*132 + cc + 1]   = acc[mf][nf][1];
                tile[(rr+8)*132 + cc]   = acc[mf][nf][2];
                tile[(rr+8)*132 + cc+1] = acc[mf][nf][3];
            }
    }
    __syncthreads();

    if constexpr (EPI == 0) {
        if (n0 < 512) {              // Q (A-side [hi|lo])
            for (int idx = tid; idx < 16384; idx += 256) {
                int r = idx >> 7, cc = idx & 127;
                float v = tile[r*132 + cc] + bias[n0 + cc];
                bf16 hi, lo; split2(v, hi, lo);
                bf16* row = g_q2 + (size_t)(m0 + r) * 1024;
                int n = n0 + cc;
                row[n] = hi; row[512 + n] = lo;
            }
        } else if (n0 < 1024) {      // K (B-side [hi|lo])
            for (int idx = tid; idx < 16384; idx += 256) {
                int r = idx >> 7, cc = idx & 127;
                float v = tile[r*132 + cc] + bias[n0 + cc];
                bf16 hi, lo; split2(v, hi, lo);
                bf16* row = g_k2 + (size_t)(m0 + r) * 1024;
                int n = n0 + cc - 512;
                row[n] = hi; row[512 + n] = lo;
            }
        } else {                     // V -> transposed [B,C, hi|lo over S]
            for (int idx = tid; idx < 16384; idx += 256) {
                int rt = idx & 127, ct = idx >> 7;
                float v = tile[rt*132 + ct] + bias[n0 + ct];
                bf16 hi, lo; split2(v, hi, lo);
                int m = m0 + rt, b = m >> 10, s = m & 1023;
                int cg = n0 + ct - 1024;
                bf16* row = g_v2 + ((size_t)b*512 + cg) * 2048;
                row[s] = hi; row[1024 + s] = lo;
            }
        }
    } else if constexpr (EPI == 1) { // scores fp32
        float* op = Out + (size_t)z * SS * SS;
        for (int idx = tid; idx < 16384; idx += 256) {
            int r = idx >> 7, cc = idx & 127;
            op[(size_t)(m0 + r) * SS + n0 + cc] = tile[r*132 + cc] * scale;
        }
    } else if constexpr (EPI == 2) { // AV out (A-side [hi|lo])
        for (int idx = tid; idx < 16384; idx += 256) {
            int r = idx >> 7, cc = idx & 127;
            float v = tile[r*132 + cc];
            bf16 hi, lo; split2(v, hi, lo);
            bf16* row = g_ao2 + ((size_t)z * SS + m0 + r) * 1024;
            int n = n0 + cc;
            row[n] = hi; row[512 + n] = lo;
        }
    } else {                         // proj: +bias +residual, NCHW transposed write
        for (int idx = tid; idx < 16384; idx += 256) {
            int rt = idx & 127, ct = idx >> 7;
            int m = m0 + rt, b = m >> 10, s = m & 1023;
            int n = n0 + ct;
            size_t oidx = ((size_t)b * 512 + n) * 1024 + s;
            Out[oidx] = tile[rt*132 + ct] + bias[n] + resid[oidx];
        }
    }
}

// ---------------- softmax over 1024-wide rows, [hi|lo] output ----------------
__global__ void softmax_rows(const float* __restrict__ sc) {
    const float* row = sc + (size_t)blockIdx.x * SS;
    bf16* orow = g_p2 + (size_t)blockIdx.x * 2048;
    int t = threadIdx.x;
    float v[4];
#pragma unroll
    for (int i = 0; i < 4; i++) v[i] = row[t + i*256];
    float m = fmaxf(fmaxf(v[0], v[1]), fmaxf(v[2], v[3]));
    __shared__ float red[8];
    for (int o = 16; o > 0; o >>= 1) m = fmaxf(m, __shfl_xor_sync(0xffffffffu, m, o));
    if ((t & 31) == 0) red[t >> 5] = m;
    __syncthreads();
    float mm = fmaxf(fmaxf(fmaxf(red[0], red[1]), fmaxf(red[2], red[3])),
                     fmaxf(fmaxf(red[4], red[5]), fmaxf(red[6], red[7])));
    float s = 0.f;
#pragma unroll
    for (int i = 0; i < 4; i++) { v[i] = __expf(v[i] - mm); s += v[i]; }
    for (int o = 16; o > 0; o >>= 1) s += __shfl_xor_sync(0xffffffffu, s, o);
    __syncthreads();
    if ((t & 31) == 0) red[t >> 5] = s;
    __syncthreads();
    float tot = ((red[0]+red[1]) + (red[2]+red[3])) + ((red[4]+red[5]) + (red[6]+red[7]));
    float invs = 1.f / tot;
#pragma unroll
    for (int i = 0; i < 4; i++) {
        float p = v[i] * invs;
        bf16 hi, lo; split2(p, hi, lo);
        int k = t + i*256;
        orow[k] = hi; orow[1024 + k] = lo;
    }
}

// ---------------- launch ----------------
extern "C" void kernel_launch(void* const* d_in, const int* in_sizes, int n_in,
                              void* d_out, int out_size) {
    const float* x      = (const float*)d_in[0];
    const float* gn_w   = (const float*)d_in[1];
    const float* gn_b   = (const float*)d_in[2];
    const float* qkv_w  = (const float*)d_in[3];
    const float* qkv_b  = (const float*)d_in[4];
    const float* proj_w = (const float*)d_in[5];
    const float* proj_b = (const float*)d_in[6];
    float* out = (float*)d_out;

    cudaFuncSetAttribute(mm_gemm<0>, cudaFuncAttributeMaxDynamicSharedMemorySize, DYN_SMEM);
    cudaFuncSetAttribute(mm_gemm<1>, cudaFuncAttributeMaxDynamicSharedMemorySize, DYN_SMEM);
    cudaFuncSetAttribute(mm_gemm<2>, cudaFuncAttributeMaxDynamicSharedMemorySize, DYN_SMEM);
    cudaFuncSetAttribute(mm_gemm<3>, cudaFuncAttributeMaxDynamicSharedMemorySize, DYN_SMEM);

    bf16 *h2, *w1, *w2, *q2, *k2, *v2, *p2, *ao2; float* sc;
    cudaGetSymbolAddress((void**)&h2,  g_h2);
    cudaGetSymbolAddress((void**)&w1,  g_w1);
    cudaGetSymbolAddress((void**)&w2,  g_w2);
    cudaGetSymbolAddress((void**)&q2,  g_q2);
    cudaGetSymbolAddress((void**)&k2,  g_k2);
    cudaGetSymbolAddress((void**)&v2,  g_v2);
    cudaGetSymbolAddress((void**)&p2,  g_p2);
    cudaGetSymbolAddress((void**)&ao2, g_ao2);
    cudaGetSymbolAddress((void**)&sc,  g_sc);

    // 1. fused weight splits
    wsplit_all<<<(2048*512 + 255)/256, 256>>>(qkv_w, proj_w);

    // 2. fused GroupNorm stats
    gn_stats<<<dim3(64, BB), 256>>>(x);

    // 3. normalize + transpose + split
    norm_split<<<dim3(SS/32, CC/32, BB), dim3(32, 8)>>>(x, gn_w, gn_b);

    // 4. QKV GEMM: M=16384, N=1536, K=1536 (logical)  <-- profiled slot
    mm_gemm<0><<<dim3(12, 128, 1), 256, DYN_SMEM>>>(
        h2, 1024, 0LL, 1024, w1, 1024, 0LL, 512,
        nullptr, qkv_b, nullptr, 1.f, 1536);

    // 5. scores = scale * Q K^T, batched: M=N=1024, K=1536 (logical)
    mm_gemm<1><<<dim3(8, 8, BB), 256, DYN_SMEM>>>(
        q2, 1024, 1024LL*1024, 1024, k2, 1024, 1024LL*1024, 512, sc,
        nullptr, nullptr, 0.044194173824159216f, 1536);

    // 6. softmax + split
    softmax_rows<<<BB*SS, 256>>>(sc);

    // 7. attn @ V: M=1024, N=512, K=3072 (logical), batched
    mm_gemm<2><<<dim3(4, 8, BB), 256, DYN_SMEM>>>(
        p2, 2048, 1024LL*2048, 2048, v2, 2048, 512LL*2048, 1024, nullptr,
        nullptr, nullptr, 1.f, 3072);

    // 8. proj + bias + residual -> NCHW out: M=16384, N=512, K=1536 (logical)
    mm_gemm<3><<<dim3(4, 128, 1), 256, DYN_SMEM>>>(
        ao2, 1024, 0LL, 1024, w2, 1024, 0LL, 512, out, proj_b, x, 1.f, 1536);
}

// round 8
// speedup vs baseline: 1.7797x; 1.6623x over previous
#include <cuda_runtime.h>
#include <cuda_fp16.h>
#include <cstdint>
#include <math.h>

#define BB 16
#define CC 512
#define SS 1024
#define PER_B (CC*SS)

typedef __half f16;

// ---------------- scratch (__device__ globals; no allocs) ----------------
__device__ float g_psum[BB*64], g_psq[BB*64], g_stats[BB*2];
__device__ unsigned g_ctr;
__device__ f16  g_h2 [(size_t)BB*SS*1024];   // norm'd [B*S, hi|lo] fp16 (A-side)
__device__ f16  g_w1 [1536*512];             // qkv_w fp16 (B-side, plain)
__device__ f16  g_w2 [512*512];              // proj_w fp16 (B-side, plain)
__device__ f16  g_q2 [(size_t)BB*SS*1024];   // Q [hi|lo] (A-side)
__device__ f16  g_k2 [(size_t)BB*SS*512];    // K fp16 plain (B-side)
__device__ f16  g_v2 [(size_t)BB*CC*1024];   // V transposed [B,C,S] fp16 plain (B-side)
__device__ f16  g_p2 [(size_t)BB*SS*2048];   // probs [B*S, hi|lo] (A-side)
__device__ f16  g_ao2[(size_t)BB*SS*1024];   // attn out [hi|lo] (A-side)
__device__ float g_sc [(size_t)BB*SS*SS];    // scores fp32

// ---------------- helpers ----------------
__device__ __forceinline__ uint32_t smem_u32(const void* p) {
    uint32_t a;
    asm("{ .reg .u64 t; cvta.to.shared.u64 t, %1; cvt.u32.u64 %0, t; }" : "=r"(a) : "l"(p));
    return a;
}
#define CP_ASYNC16(dst, src) \
    asm volatile("cp.async.cg.shared.global [%0], [%1], 16;" :: "r"(dst), "l"(src) : "memory")
#define CP_COMMIT() asm volatile("cp.async.commit_group;" ::: "memory")
#define CP_WAIT0()  asm volatile("cp.async.wait_group 0;" ::: "memory")
#define CP_WAIT1()  asm volatile("cp.async.wait_group 1;" ::: "memory")
#define LDM_X4(r0,r1,r2,r3,addr) \
    asm volatile("ldmatrix.sync.aligned.m8n8.x4.shared.b16 {%0,%1,%2,%3}, [%4];" \
        : "=r"(r0),"=r"(r1),"=r"(r2),"=r"(r3) : "r"(addr))
#define MMA16816(d, a, b0, b1) \
    asm volatile("mma.sync.aligned.m16n8k16.row.col.f32.f16.f16.f32 " \
        "{%0,%1,%2,%3}, {%4,%5,%6,%7}, {%8,%9}, {%0,%1,%2,%3};" \
        : "+f"((d)[0]), "+f"((d)[1]), "+f"((d)[2]), "+f"((d)[3]) \
        : "r"((a)[0]), "r"((a)[1]), "r"((a)[2]), "r"((a)[3]), "r"(b0), "r"(b1))

__device__ __forceinline__ void split2h(float v, f16& hi, f16& lo) {
    hi = __float2half_rn(v);
    lo = __float2half_rn(v - __half2float(hi));
}

// ---------------- weight convert (plain fp16) ----------------
__global__ void wconv(const float* __restrict__ w1s, const float* __restrict__ w2s) {
    int i = blockIdx.x * 256 + threadIdx.x;
    if (i < 2048*512) {
        if (i < 1536*512) g_w1[i] = __float2half_rn(w1s[i]);
        else              g_w2[i - 1536*512] = __float2half_rn(w2s[i - 1536*512]);
    }
}

// ---------------- fused GroupNorm stats (partial + last-block finalize) ----------------
__global__ void gn_stats(const float* __restrict__ x) {
    int b = blockIdx.y, chunk = blockIdx.x, t = threadIdx.x;
    const float* p = x + (size_t)b*PER_B + (size_t)chunk*8192;
    float s = 0.f, q = 0.f;
#pragma unroll
    for (int i = 0; i < 32; i++) { float v = p[t + i*256]; s += v; q += v*v; }
    __shared__ float ss_[8], sq_[8];
    for (int o = 16; o > 0; o >>= 1) {
        s += __shfl_down_sync(0xffffffffu, s, o);
        q += __shfl_down_sync(0xffffffffu, q, o);
    }
    if ((t & 31) == 0) { ss_[t >> 5] = s; sq_[t >> 5] = q; }
    __syncthreads();
    __shared__ int isLast;
    if (t == 0) {
        float S2 = 0.f, Q2 = 0.f;
#pragma unroll
        for (int i = 0; i < 8; i++) { S2 += ss_[i]; Q2 += sq_[i]; }
        g_psum[b*64 + chunk] = S2; g_psq[b*64 + chunk] = Q2;
        __threadfence();
        unsigned v = atomicAdd(&g_ctr, 1u);
        isLast = (v == 64u*BB - 1u);
    }
    __syncthreads();
    if (isLast) {
        if (t < BB) {
            float s2 = 0.f, q2 = 0.f;
            for (int i = 0; i < 64; i++) { s2 += g_psum[t*64+i]; q2 += g_psq[t*64+i]; }
            float mean = s2 * (1.f/(float)PER_B);
            float var  = q2 * (1.f/(float)PER_B) - mean*mean;
            g_stats[2*t] = mean; g_stats[2*t+1] = rsqrtf(var + 1e-5f);
        }
        if (t == 0) g_ctr = 0u;
    }
}

// ---------------- normalize + transpose + split -> g_h2 [B*S, hi|lo] ----------------
__global__ void norm_split(const float* __restrict__ x,
                           const float* __restrict__ gw,
                           const float* __restrict__ gb) {
    __shared__ float tile[32][33];
    int b = blockIdx.z;
    int s0 = blockIdx.x * 32, c0 = blockIdx.y * 32;
    int tx = threadIdx.x, ty = threadIdx.y;
    const float* xp = x + (size_t)b * PER_B;
#pragma unroll
    for (int i = 0; i < 4; i++) {
        int c = c0 + ty + i*8;
        tile[ty + i*8][tx] = xp[(size_t)c*SS + s0 + tx];
    }
    __syncthreads();
    float mean = g_stats[2*b], inv = g_stats[2*b+1];
    int c = c0 + tx;
    float w  = gw[c] * inv;
    float bias = gb[c] - mean * w;
#pragma unroll
    for (int i = 0; i < 4; i++) {
        int s = s0 + ty + i*8;
        float v = tile[tx][ty + i*8] * w + bias;
        f16 hi, lo; split2h(v, hi, lo);
        f16* row = g_h2 + ((size_t)b*SS + s) * 1024;
        row[c] = hi; row[512 + c] = lo;
    }
}

// ---------------- HMMA GEMM: 128x128 CTA, 8 warps (32x64 each), BK=32, 3-stage ----------------
// NT logical: out[m,n] = sum_k A[m,k_effA]*B[n,k_effB], k_eff = k>=thresh ? k-thresh : k
// EPI: 0 = QKV out, 1 = scores*scale, 2 = AV out, 3 = proj+bias+resid (NCHW)
#define STAGE_BYTES 20480        // A 128x80 (10240) + B 128x80 (10240)
#define DYN_SMEM 67584           // max(3*20480=61440, 128*132*4=67584)

__device__ __forceinline__ void prefetch_tile(char* smem, int stage,
    const f16* __restrict__ A, int lda, const f16* __restrict__ B, int ldb,
    int m0, int n0, int kA, int kB, int tid)
{
    char* as = smem + stage*STAGE_BYTES;
    char* bs = as + 10240;
    int row = tid >> 1, seg = tid & 1;
    const f16* ag = A + (size_t)(m0 + row)*lda + kA + seg*16;
    const f16* bg = B + (size_t)(n0 + row)*ldb + kB + seg*16;
    uint32_t asw = smem_u32(as + row*80 + seg*32);
    uint32_t bsw = smem_u32(bs + row*80 + seg*32);
    CP_ASYNC16(asw,      (const void*)ag);
    CP_ASYNC16(asw + 16, (const void*)(ag + 8));
    CP_ASYNC16(bsw,      (const void*)bg);
    CP_ASYNC16(bsw + 16, (const void*)(bg + 8));
}

template<int EPI>
__global__ __launch_bounds__(256, 2)
void mm_gemm(const f16* __restrict__ A, int lda, long long sA, int thA,
             const f16* __restrict__ B, int ldb, long long sB, int thB,
             float* __restrict__ Out,
             const float* __restrict__ bias,
             const float* __restrict__ resid,
             float scale, int K)
{
    extern __shared__ char smem[];
    int tid = threadIdx.x, lane = tid & 31, wid = tid >> 5;
    int wm = wid >> 1, wn = wid & 1;          // 4 x 2 warp grid, 32x64 tiles
    int z = blockIdx.z;
    int m0 = blockIdx.y * 128, n0 = blockIdx.x * 128;
    A += (size_t)z * sA;
    B += (size_t)z * sB;

    float acc[2][8][4];
#pragma unroll
    for (int i = 0; i < 2; i++)
#pragma unroll
        for (int j = 0; j < 8; j++)
#pragma unroll
            for (int r = 0; r < 4; r++) acc[i][j][r] = 0.f;

    uint32_t a_off = (uint32_t)((wm*32 + (lane & 15)) * 80 + (lane >> 4) * 16);
    uint32_t b_off = (uint32_t)((wn*64 + (lane & 7) + ((lane >> 4) << 3)) * 80
                                + ((lane >> 3) & 1) * 16);
    uint32_t smem_base = smem_u32(smem);

    int nch = K >> 5;
    {
        prefetch_tile(smem, 0, A, lda, B, ldb, m0, n0, 0, 0, tid);
        CP_COMMIT();
        int k0 = 32;
        prefetch_tile(smem, 1, A, lda, B, ldb, m0, n0,
                      (k0 >= thA) ? k0 - thA : k0, (k0 >= thB) ? k0 - thB : k0, tid);
        CP_COMMIT();
    }

    int st = 0;
    for (int c = 0; c < nch; c++) {
        if (c + 2 <= nch) CP_WAIT1(); else CP_WAIT0();
        __syncthreads();
        if (c + 2 < nch) {
            int k0 = (c + 2) * 32;
            int nst = st + 2; if (nst >= 3) nst -= 3;
            prefetch_tile(smem, nst, A, lda, B, ldb, m0, n0,
                          (k0 >= thA) ? k0 - thA : k0, (k0 >= thB) ? k0 - thB : k0, tid);
            CP_COMMIT();
        }

        uint32_t as_b = smem_base + st*STAGE_BYTES + a_off;
        uint32_t bs_b = smem_base + st*STAGE_BYTES + 10240 + b_off;
#pragma unroll
        for (int ks = 0; ks < 2; ks++) {
            uint32_t a[2][4], b[4][4];
#pragma unroll
            for (int mf = 0; mf < 2; mf++)
                LDM_X4(a[mf][0], a[mf][1], a[mf][2], a[mf][3], as_b + mf*1280 + ks*32);
#pragma unroll
            for (int nf2 = 0; nf2 < 4; nf2++)
                LDM_X4(b[nf2][0], b[nf2][1], b[nf2][2], b[nf2][3], bs_b + nf2*1280 + ks*32);
#pragma unroll
            for (int mf = 0; mf < 2; mf++)
#pragma unroll
                for (int nf = 0; nf < 8; nf++)
                    MMA16816(acc[mf][nf], a[mf], b[nf>>1][(nf&1)*2], b[nf>>1][(nf&1)*2+1]);
        }
        st++; if (st == 3) st = 0;
    }
    __syncthreads();

    // stage accumulators to smem fp32 [128][132]
    float* tile = (float*)smem;
    {
        int r = lane >> 2, cp = (lane & 3) * 2;
#pragma unroll
        for (int mf = 0; mf < 2; mf++)
#pragma unroll
            for (int nf = 0; nf < 8; nf++) {
                int rr = wm*32 + mf*16 + r, cc = wn*64 + nf*8 + cp;
                tile[rr*132 + cc]       = acc[mf][nf][0];
                tile[rr*132 + cc + 1]   = acc[mf][nf][1];
                tile[(rr+8)*132 + cc]   = acc[mf][nf][2];
                tile[(rr+8)*132 + cc+1] = acc[mf][nf][3];
            }
    }
    __syncthreads();

    if constexpr (EPI == 0) {
        if (n0 < 512) {              // Q (A-side [hi|lo])
            for (int idx = tid; idx < 16384; idx += 256) {
                int r = idx >> 7, cc = idx & 127;
                float v = tile[r*132 + cc] + bias[n0 + cc];
                f16 hi, lo; split2h(v, hi, lo);
                f16* row = g_q2 + (size_t)(m0 + r) * 1024;
                int n = n0 + cc;
                row[n] = hi; row[512 + n] = lo;
            }
        } else if (n0 < 1024) {      // K (B-side plain fp16)
            for (int idx = tid; idx < 16384; idx += 256) {
                int r = idx >> 7, cc = idx & 127;
                float v = tile[r*132 + cc] + bias[n0 + cc];
                g_k2[(size_t)(m0 + r) * 512 + n0 + cc - 512] = __float2half_rn(v);
            }
        } else {                     // V -> transposed [B,C,S] plain fp16
            for (int idx = tid; idx < 16384; idx += 256) {
                int rt = idx & 127, ct = idx >> 7;
                float v = tile[rt*132 + ct] + bias[n0 + ct];
                int m = m0 + rt, b = m >> 10, s = m & 1023;
                int cg = n0 + ct - 1024;
                g_v2[((size_t)b*512 + cg) * 1024 + s] = __float2half_rn(v);
            }
        }
    } else if constexpr (EPI == 1) { // scores fp32
        float* op = Out + (size_t)z * SS * SS;
        for (int idx = tid; idx < 16384; idx += 256) {
            int r = idx >> 7, cc = idx & 127;
            op[(size_t)(m0 + r) * SS + n0 + cc] = tile[r*132 + cc] * scale;
        }
    } else if constexpr (EPI == 2) { // AV out (A-side [hi|lo])
        for (int idx = tid; idx < 16384; idx += 256) {
            int r = idx >> 7, cc = idx & 127;
            float v = tile[r*132 + cc];
            f16 hi, lo; split2h(v, hi, lo);
            f16* row = g_ao2 + ((size_t)z * SS + m0 + r) * 1024;
            int n = n0 + cc;
            row[n] = hi; row[512 + n] = lo;
        }
    } else {                         // proj: +bias +residual, NCHW transposed write
        for (int idx = tid; idx < 16384; idx += 256) {
            int rt = idx & 127, ct = idx >> 7;
            int m = m0 + rt, b = m >> 10, s = m & 1023;
            int n = n0 + ct;
            size_t oidx = ((size_t)b * 512 + n) * 1024 + s;
            Out[oidx] = tile[rt*132 + ct] + bias[n] + resid[oidx];
        }
    }
}

// ---------------- softmax over 1024-wide rows, [hi|lo] fp16 output ----------------
__global__ void softmax_rows(const float* __restrict__ sc) {
    const float* row = sc + (size_t)blockIdx.x * SS;
    f16* orow = g_p2 + (size_t)blockIdx.x * 2048;
    int t = threadIdx.x;
    float v[4];
#pragma unroll
    for (int i = 0; i < 4; i++) v[i] = row[t + i*256];
    float m = fmaxf(fmaxf(v[0], v[1]), fmaxf(v[2], v[3]));
    __shared__ float red[8];
    for (int o = 16; o > 0; o >>= 1) m = fmaxf(m, __shfl_xor_sync(0xffffffffu, m, o));
    if ((t & 31) == 0) red[t >> 5] = m;
    __syncthreads();
    float mm = fmaxf(fmaxf(fmaxf(red[0], red[1]), fmaxf(red[2], red[3])),
                     fmaxf(fmaxf(red[4], red[5]), fmaxf(red[6], red[7])));
    float s = 0.f;
#pragma unroll
    for (int i = 0; i < 4; i++) { v[i] = __expf(v[i] - mm); s += v[i]; }
    for (int o = 16; o > 0; o >>= 1) s += __shfl_xor_sync(0xffffffffu, s, o);
    __syncthreads();
    if ((t & 31) == 0) red[t >> 5] = s;
    __syncthreads();
    float tot = ((red[0]+red[1]) + (red[2]+red[3])) + ((red[4]+red[5]) + (red[6]+red[7]));
    float invs = 1.f / tot;
#pragma unroll
    for (int i = 0; i < 4; i++) {
        float p = v[i] * invs;
        f16 hi, lo; split2h(p, hi, lo);
        int k = t + i*256;
        orow[k] = hi; orow[1024 + k] = lo;
    }
}

// ---------------- launch ----------------
extern "C" void kernel_launch(void* const* d_in, const int* in_sizes, int n_in,
                              void* d_out, int out_size) {
    const float* x      = (const float*)d_in[0];
    const float* gn_w   = (const float*)d_in[1];
    const float* gn_b   = (const float*)d_in[2];
    const float* qkv_w  = (const float*)d_in[3];
    const float* qkv_b  = (const float*)d_in[4];
    const float* proj_w = (const float*)d_in[5];
    const float* proj_b = (const float*)d_in[6];
    float* out = (float*)d_out;

    cudaFuncSetAttribute(mm_gemm<0>, cudaFuncAttributeMaxDynamicSharedMemorySize, DYN_SMEM);
    cudaFuncSetAttribute(mm_gemm<1>, cudaFuncAttributeMaxDynamicSharedMemorySize, DYN_SMEM);
    cudaFuncSetAttribute(mm_gemm<2>, cudaFuncAttributeMaxDynamicSharedMemorySize, DYN_SMEM);
    cudaFuncSetAttribute(mm_gemm<3>, cudaFuncAttributeMaxDynamicSharedMemorySize, DYN_SMEM);

    f16 *h2, *w1, *w2, *q2, *k2, *v2, *p2, *ao2; float* sc;
    cudaGetSymbolAddress((void**)&h2,  g_h2);
    cudaGetSymbolAddress((void**)&w1,  g_w1);
    cudaGetSymbolAddress((void**)&w2,  g_w2);
    cudaGetSymbolAddress((void**)&q2,  g_q2);
    cudaGetSymbolAddress((void**)&k2,  g_k2);
    cudaGetSymbolAddress((void**)&v2,  g_v2);
    cudaGetSymbolAddress((void**)&p2,  g_p2);
    cudaGetSymbolAddress((void**)&ao2, g_ao2);
    cudaGetSymbolAddress((void**)&sc,  g_sc);

    // 1. weight convert (plain fp16)
    wconv<<<(2048*512 + 255)/256, 256>>>(qkv_w, proj_w);

    // 2. fused GroupNorm stats
    gn_stats<<<dim3(64, BB), 256>>>(x);

    // 3. normalize + transpose + split (fp16 hi|lo)
    norm_split<<<dim3(SS/32, CC/32, BB), dim3(32, 8)>>>(x, gn_w, gn_b);

    // 4. QKV GEMM: M=16384, N=1536, K=1024 logical (A=[hi|lo], B folds at 512)
    mm_gemm<0><<<dim3(12, 128, 1), 256, DYN_SMEM>>>(
        h2, 1024, 0LL, 1024, w1, 512, 0LL, 512,
        nullptr, qkv_b, nullptr, 1.f, 1024);

    // 5. scores = scale * Q K^T, batched: K=1024 logical
    mm_gemm<1><<<dim3(8, 8, BB), 256, DYN_SMEM>>>(
        q2, 1024, 1024LL*1024, 1024, k2, 512, 1024LL*512, 512, sc,
        nullptr, nullptr, 0.044194173824159216f, 1024);

    // 6. softmax + split
    softmax_rows<<<BB*SS, 256>>>(sc);

    // 7. attn @ V: M=1024, N=512, K=2048 logical, batched
    mm_gemm<2><<<dim3(4, 8, BB), 256, DYN_SMEM>>>(
        p2, 2048, 1024LL*2048, 2048, v2, 1024, 512LL*1024, 1024, nullptr,
        nullptr, nullptr, 1.f, 2048);

    // 8. proj + bias + residual -> NCHW out: K=1024 logical
    mm_gemm<3><<<dim3(4, 128, 1), 256, DYN_SMEM>>>(
        ao2, 1024, 0LL, 1024, w2, 512, 0LL, 512, out, proj_b, x, 1.f, 1024);
}

// round 9
// speedup vs baseline: 3.0173x; 1.6954x over previous
#include <cuda_runtime.h>
#include <cuda_fp16.h>
#include <cstdint>
#include <math.h>

#define BB 16
#define CC 512
#define SS 1024
#define PER_B (CC*SS)

typedef __half f16;

// ---------------- scratch (__device__ globals; no allocs) ----------------
__device__ float g_psum[BB*64], g_psq[BB*64], g_stats[BB*2];
__device__ unsigned g_ctr;
__device__ f16  g_h2 [(size_t)BB*SS*512];    // norm'd [B*S, C] fp16 (A-side)
__device__ f16  g_w1 [1536*512];             // qkv_w fp16 (B-side)
__device__ f16  g_w2 [512*512];              // proj_w fp16 (B-side)
__device__ f16  g_q2 [(size_t)BB*SS*512];    // Q fp16 (A-side)
__device__ f16  g_k2 [(size_t)BB*SS*512];    // K fp16 (B-side)
__device__ f16  g_v2 [(size_t)BB*CC*1024];   // V transposed [B,C,S] fp16 (B-side)
__device__ f16  g_p2 [(size_t)BB*SS*1024];   // probs [B*S, S] fp16 (A-side)
__device__ f16  g_ao2[(size_t)BB*SS*512];    // attn out fp16 (A-side)
__device__ float g_sc [(size_t)BB*SS*SS];    // scores fp32

// ---------------- helpers ----------------
__device__ __forceinline__ uint32_t smem_u32(const void* p) {
    uint32_t a;
    asm("{ .reg .u64 t; cvta.to.shared.u64 t, %1; cvt.u32.u64 %0, t; }" : "=r"(a) : "l"(p));
    return a;
}
#define CP_ASYNC16(dst, src) \
    asm volatile("cp.async.cg.shared.global [%0], [%1], 16;" :: "r"(dst), "l"(src) : "memory")
#define CP_COMMIT() asm volatile("cp.async.commit_group;" ::: "memory")
#define CP_WAIT0()  asm volatile("cp.async.wait_group 0;" ::: "memory")
#define CP_WAIT1()  asm volatile("cp.async.wait_group 1;" ::: "memory")
#define LDM_X4(r0,r1,r2,r3,addr) \
    asm volatile("ldmatrix.sync.aligned.m8n8.x4.shared.b16 {%0,%1,%2,%3}, [%4];" \
        : "=r"(r0),"=r"(r1),"=r"(r2),"=r"(r3) : "r"(addr))
#define MMA16816(d, a, b0, b1) \
    asm volatile("mma.sync.aligned.m16n8k16.row.col.f32.f16.f16.f32 " \
        "{%0,%1,%2,%3}, {%4,%5,%6,%7}, {%8,%9}, {%0,%1,%2,%3};" \
        : "+f"((d)[0]), "+f"((d)[1]), "+f"((d)[2]), "+f"((d)[3]) \
        : "r"((a)[0]), "r"((a)[1]), "r"((a)[2]), "r"((a)[3]), "r"(b0), "r"(b1))

// ---------------- weight convert (plain fp16) ----------------
__global__ void wconv(const float* __restrict__ w1s, const float* __restrict__ w2s) {
    int i = blockIdx.x * 256 + threadIdx.x;
    if (i < 2048*512) {
        if (i < 1536*512) g_w1[i] = __float2half_rn(w1s[i]);
        else              g_w2[i - 1536*512] = __float2half_rn(w2s[i - 1536*512]);
    }
}

// ---------------- fused GroupNorm stats (partial + last-block finalize) ----------------
__global__ void gn_stats(const float* __restrict__ x) {
    int b = blockIdx.y, chunk = blockIdx.x, t = threadIdx.x;
    const float* p = x + (size_t)b*PER_B + (size_t)chunk*8192;
    float s = 0.f, q = 0.f;
#pragma unroll
    for (int i = 0; i < 32; i++) { float v = p[t + i*256]; s += v; q += v*v; }
    __shared__ float ss_[8], sq_[8];
    for (int o = 16; o > 0; o >>= 1) {
        s += __shfl_down_sync(0xffffffffu, s, o);
        q += __shfl_down_sync(0xffffffffu, q, o);
    }
    if ((t & 31) == 0) { ss_[t >> 5] = s; sq_[t >> 5] = q; }
    __syncthreads();
    __shared__ int isLast;
    if (t == 0) {
        float S2 = 0.f, Q2 = 0.f;
#pragma unroll
        for (int i = 0; i < 8; i++) { S2 += ss_[i]; Q2 += sq_[i]; }
        g_psum[b*64 + chunk] = S2; g_psq[b*64 + chunk] = Q2;
        __threadfence();
        unsigned v = atomicAdd(&g_ctr, 1u);
        isLast = (v == 64u*BB - 1u);
    }
    __syncthreads();
    if (isLast) {
        if (t < BB) {
            float s2 = 0.f, q2 = 0.f;
            for (int i = 0; i < 64; i++) { s2 += g_psum[t*64+i]; q2 += g_psq[t*64+i]; }
            float mean = s2 * (1.f/(float)PER_B);
            float var  = q2 * (1.f/(float)PER_B) - mean*mean;
            g_stats[2*t] = mean; g_stats[2*t+1] = rsqrtf(var + 1e-5f);
        }
        if (t == 0) g_ctr = 0u;
    }
}

// ---------------- normalize + transpose -> g_h2 [B*S, C] fp16 ----------------
__global__ void norm_split(const float* __restrict__ x,
                           const float* __restrict__ gw,
                           const float* __restrict__ gb) {
    __shared__ float tile[32][33];
    int b = blockIdx.z;
    int s0 = blockIdx.x * 32, c0 = blockIdx.y * 32;
    int tx = threadIdx.x, ty = threadIdx.y;
    const float* xp = x + (size_t)b * PER_B;
#pragma unroll
    for (int i = 0; i < 4; i++) {
        int c = c0 + ty + i*8;
        tile[ty + i*8][tx] = xp[(size_t)c*SS + s0 + tx];
    }
    __syncthreads();
    float mean = g_stats[2*b], inv = g_stats[2*b+1];
    int c = c0 + tx;
    float w  = gw[c] * inv;
    float bias = gb[c] - mean * w;
#pragma unroll
    for (int i = 0; i < 4; i++) {
        int s = s0 + ty + i*8;
        float v = tile[tx][ty + i*8] * w + bias;
        g_h2[((size_t)b*SS + s) * 512 + c] = __float2half_rn(v);
    }
}

// ---------------- HMMA GEMM: 128x128 CTA, 8 warps (32x64 each), BK=32, 3-stage ----------------
// NT: out[m,n] = sum_k A[m,k]*B[n,k]
// EPI: 0 = QKV out, 1 = scores*scale, 2 = AV out, 3 = proj+bias+resid (NCHW)
#define STAGE_BYTES 20480        // A 128x80 (10240) + B 128x80 (10240)
#define DYN_SMEM 67584           // max(3*20480=61440, 128*132*4=67584)

__device__ __forceinline__ void prefetch_tile(char* smem, int stage,
    const f16* __restrict__ A, int lda, const f16* __restrict__ B, int ldb,
    int m0, int n0, int k0, int tid)
{
    char* as = smem + stage*STAGE_BYTES;
    char* bs = as + 10240;
    int row = tid >> 1, seg = tid & 1;
    const f16* ag = A + (size_t)(m0 + row)*lda + k0 + seg*16;
    const f16* bg = B + (size_t)(n0 + row)*ldb + k0 + seg*16;
    uint32_t asw = smem_u32(as + row*80 + seg*32);
    uint32_t bsw = smem_u32(bs + row*80 + seg*32);
    CP_ASYNC16(asw,      (const void*)ag);
    CP_ASYNC16(asw + 16, (const void*)(ag + 8));
    CP_ASYNC16(bsw,      (const void*)bg);
    CP_ASYNC16(bsw + 16, (const void*)(bg + 8));
}

template<int EPI>
__global__ __launch_bounds__(256, 2)
void mm_gemm(const f16* __restrict__ A, int lda, long long sA,
             const f16* __restrict__ B, int ldb, long long sB,
             float* __restrict__ Out,
             const float* __restrict__ bias,
             const float* __restrict__ resid,
             float scale, int K)
{
    extern __shared__ char smem[];
    int tid = threadIdx.x, lane = tid & 31, wid = tid >> 5;
    int wm = wid >> 1, wn = wid & 1;          // 4 x 2 warp grid, 32x64 tiles
    int z = blockIdx.z;
    int m0 = blockIdx.y * 128, n0 = blockIdx.x * 128;
    A += (size_t)z * sA;
    B += (size_t)z * sB;

    float acc[2][8][4];
#pragma unroll
    for (int i = 0; i < 2; i++)
#pragma unroll
        for (int j = 0; j < 8; j++)
#pragma unroll
            for (int r = 0; r < 4; r++) acc[i][j][r] = 0.f;

    uint32_t a_off = (uint32_t)((wm*32 + (lane & 15)) * 80 + (lane >> 4) * 16);
    uint32_t b_off = (uint32_t)((wn*64 + (lane & 7) + ((lane >> 4) << 3)) * 80
                                + ((lane >> 3) & 1) * 16);
    uint32_t smem_base = smem_u32(smem);

    int nch = K >> 5;
    prefetch_tile(smem, 0, A, lda, B, ldb, m0, n0, 0, tid);
    CP_COMMIT();
    prefetch_tile(smem, 1, A, lda, B, ldb, m0, n0, 32, tid);
    CP_COMMIT();

    int st = 0;
    for (int c = 0; c < nch; c++) {
        if (c + 2 <= nch) CP_WAIT1(); else CP_WAIT0();
        __syncthreads();
        if (c + 2 < nch) {
            int nst = st + 2; if (nst >= 3) nst -= 3;
            prefetch_tile(smem, nst, A, lda, B, ldb, m0, n0, (c+2)*32, tid);
            CP_COMMIT();
        }

        uint32_t as_b = smem_base + st*STAGE_BYTES + a_off;
        uint32_t bs_b = smem_base + st*STAGE_BYTES + 10240 + b_off;
#pragma unroll
        for (int ks = 0; ks < 2; ks++) {
            uint32_t a[2][4], b[4][4];
#pragma unroll
            for (int mf = 0; mf < 2; mf++)
                LDM_X4(a[mf][0], a[mf][1], a[mf][2], a[mf][3], as_b + mf*1280 + ks*32);
#pragma unroll
            for (int nf2 = 0; nf2 < 4; nf2++)
                LDM_X4(b[nf2][0], b[nf2][1], b[nf2][2], b[nf2][3], bs_b + nf2*1280 + ks*32);
#pragma unroll
            for (int mf = 0; mf < 2; mf++)
#pragma unroll
                for (int nf = 0; nf < 8; nf++)
                    MMA16816(acc[mf][nf], a[mf], b[nf>>1][(nf&1)*2], b[nf>>1][(nf&1)*2+1]);
        }
        st++; if (st == 3) st = 0;
    }
    __syncthreads();

    // stage accumulators to smem fp32 [128][132]
    float* tile = (float*)smem;
    {
        int r = lane >> 2, cp = (lane & 3) * 2;
#pragma unroll
        for (int mf = 0; mf < 2; mf++)
#pragma unroll
            for (int nf = 0; nf < 8; nf++) {
                int rr = wm*32 + mf*16 + r, cc = wn*64 + nf*8 + cp;
                tile[rr*132 + cc]       = acc[mf][nf][0];
                tile[rr*132 + cc + 1]   = acc[mf][nf][1];
                tile[(rr+8)*132 + cc]   = acc[mf][nf][2];
                tile[(rr+8)*132 + cc+1] = acc[mf][nf][3];
            }
    }
    __syncthreads();

    if constexpr (EPI == 0) {
        if (n0 < 512) {              // Q plain fp16
            for (int idx = tid; idx < 16384; idx += 256) {
                int r = idx >> 7, cc = idx & 127;
                float v = tile[r*132 + cc] + bias[n0 + cc];
                g_q2[(size_t)(m0 + r) * 512 + n0 + cc] = __float2half_rn(v);
            }
        } else if (n0 < 1024) {      // K plain fp16
            for (int idx = tid; idx < 16384; idx += 256) {
                int r = idx >> 7, cc = idx & 127;
                float v = tile[r*132 + cc] + bias[n0 + cc];
                g_k2[(size_t)(m0 + r) * 512 + n0 + cc - 512] = __float2half_rn(v);
            }
        } else {                     // V -> transposed [B,C,S] plain fp16
            for (int idx = tid; idx < 16384; idx += 256) {
                int rt = idx & 127, ct = idx >> 7;
                float v = tile[rt*132 + ct] + bias[n0 + ct];
                int m = m0 + rt, b = m >> 10, s = m & 1023;
                int cg = n0 + ct - 1024;
                g_v2[((size_t)b*512 + cg) * 1024 + s] = __float2half_rn(v);
            }
        }
    } else if constexpr (EPI == 1) { // scores fp32
        float* op = Out + (size_t)z * SS * SS;
        for (int idx = tid; idx < 16384; idx += 256) {
            int r = idx >> 7, cc = idx & 127;
            op[(size_t)(m0 + r) * SS + n0 + cc] = tile[r*132 + cc] * scale;
        }
    } else if constexpr (EPI == 2) { // AV out plain fp16
        for (int idx = tid; idx < 16384; idx += 256) {
            int r = idx >> 7, cc = idx & 127;
            g_ao2[((size_t)z * SS + m0 + r) * 512 + n0 + cc] =
                __float2half_rn(tile[r*132 + cc]);
        }
    } else {                         // proj: +bias +residual, NCHW transposed write
        for (int idx = tid; idx < 16384; idx += 256) {
            int rt = idx & 127, ct = idx >> 7;
            int m = m0 + rt, b = m >> 10, s = m & 1023;
            int n = n0 + ct;
            size_t oidx = ((size_t)b * 512 + n) * 1024 + s;
            Out[oidx] = tile[rt*132 + ct] + bias[n] + resid[oidx];
        }
    }
}

// ---------------- softmax over 1024-wide rows, plain fp16 output ----------------
__global__ void softmax_rows(const float* __restrict__ sc) {
    const float* row = sc + (size_t)blockIdx.x * SS;
    f16* orow = g_p2 + (size_t)blockIdx.x * 1024;
    int t = threadIdx.x;
    float v[4];
#pragma unroll
    for (int i = 0; i < 4; i++) v[i] = row[t + i*256];
    float m = fmaxf(fmaxf(v[0], v[1]), fmaxf(v[2], v[3]));
    __shared__ float red[8];
    for (int o = 16; o > 0; o >>= 1) m = fmaxf(m, __shfl_xor_sync(0xffffffffu, m, o));
    if ((t & 31) == 0) red[t >> 5] = m;
    __syncthreads();
    float mm = fmaxf(fmaxf(fmaxf(red[0], red[1]), fmaxf(red[2], red[3])),
                     fmaxf(fmaxf(red[4], red[5]), fmaxf(red[6], red[7])));
    float s = 0.f;
#pragma unroll
    for (int i = 0; i < 4; i++) { v[i] = __expf(v[i] - mm); s += v[i]; }
    for (int o = 16; o > 0; o >>= 1) s += __shfl_xor_sync(0xffffffffu, s, o);
    __syncthreads();
    if ((t & 31) == 0) red[t >> 5] = s;
    __syncthreads();
    float tot = ((red[0]+red[1]) + (red[2]+red[3])) + ((red[4]+red[5]) + (red[6]+red[7]));
    float invs = 1.f / tot;
#pragma unroll
    for (int i = 0; i < 4; i++)
        orow[t + i*256] = __float2half_rn(v[i] * invs);
}

// ---------------- launch ----------------
extern "C" void kernel_launch(void* const* d_in, const int* in_sizes, int n_in,
                              void* d_out, int out_size) {
    const float* x      = (const float*)d_in[0];
    const float* gn_w   = (const float*)d_in[1];
    const float* gn_b   = (const float*)d_in[2];
    const float* qkv_w  = (const float*)d_in[3];
    const float* qkv_b  = (const float*)d_in[4];
    const float* proj_w = (const float*)d_in[5];
    const float* proj_b = (const float*)d_in[6];
    float* out = (float*)d_out;

    cudaFuncSetAttribute(mm_gemm<0>, cudaFuncAttributeMaxDynamicSharedMemorySize, DYN_SMEM);
    cudaFuncSetAttribute(mm_gemm<1>, cudaFuncAttributeMaxDynamicSharedMemorySize, DYN_SMEM);
    cudaFuncSetAttribute(mm_gemm<2>, cudaFuncAttributeMaxDynamicSharedMemorySize, DYN_SMEM);
    cudaFuncSetAttribute(mm_gemm<3>, cudaFuncAttributeMaxDynamicSharedMemorySize, DYN_SMEM);

    f16 *h2, *w1, *w2, *q2, *k2, *v2, *p2, *ao2; float* sc;
    cudaGetSymbolAddress((void**)&h2,  g_h2);
    cudaGetSymbolAddress((void**)&w1,  g_w1);
    cudaGetSymbolAddress((void**)&w2,  g_w2);
    cudaGetSymbolAddress((void**)&q2,  g_q2);
    cudaGetSymbolAddress((void**)&k2,  g_k2);
    cudaGetSymbolAddress((void**)&v2,  g_v2);
    cudaGetSymbolAddress((void**)&p2,  g_p2);
    cudaGetSymbolAddress((void**)&ao2, g_ao2);
    cudaGetSymbolAddress((void**)&sc,  g_sc);

    // 1. weight convert
    wconv<<<(2048*512 + 255)/256, 256>>>(qkv_w, proj_w);

    // 2. fused GroupNorm stats
    gn_stats<<<dim3(64, BB), 256>>>(x);

    // 3. normalize + transpose (fp16)
    norm_split<<<dim3(SS/32, CC/32, BB), dim3(32, 8)>>>(x, gn_w, gn_b);

    // 4. QKV GEMM: M=16384, N=1536, K=512
    mm_gemm<0><<<dim3(12, 128, 1), 256, DYN_SMEM>>>(
        h2, 512, 0LL, w1, 512, 0LL,
        nullptr, qkv_b, nullptr, 1.f, 512);

    // 5. scores = scale * Q K^T, batched: K=512
    mm_gemm<1><<<dim3(8, 8, BB), 256, DYN_SMEM>>>(
        q2, 512, 1024LL*512, k2, 512, 1024LL*512, sc,
        nullptr, nullptr, 0.044194173824159216f, 512);

    // 6. softmax
    softmax_rows<<<BB*SS, 256>>>(sc);

    // 7. attn @ V: M=1024, N=512, K=1024, batched
    mm_gemm<2><<<dim3(4, 8, BB), 256, DYN_SMEM>>>(
        p2, 1024, 1024LL*1024, v2, 1024, 512LL*1024, nullptr,
        nullptr, nullptr, 1.f, 1024);

    // 8. proj + bias + residual -> NCHW out: K=512
    mm_gemm<3><<<dim3(4, 128, 1), 256, DYN_SMEM>>>(
        ao2, 512, 0LL, w2, 512, 0LL, out, proj_b, x, 1.f, 512);
}

// round 10
// speedup vs baseline: 3.1731x; 1.0516x over previous
#include <cuda_runtime.h>
#include <cuda_fp16.h>
#include <cstdint>
#include <math.h>

#define BB 16
#define CC 512
#define SS 1024
#define PER_B (CC*SS)

typedef __half f16;

// ---------------- scratch (__device__ globals; no allocs) ----------------
__device__ float g_psum[BB*64], g_psq[BB*64], g_stats[BB*2];
__device__ unsigned g_ctr;
__device__ f16  g_h2 [(size_t)BB*SS*512];    // norm'd [B*S, C] fp16 (A-side)
__device__ f16  g_w1 [1536*512];             // qkv_w fp16 (B-side)
__device__ f16  g_w2 [512*512];              // proj_w fp16 (A-side for proj)
__device__ f16  g_q2 [(size_t)BB*SS*512];    // Q fp16 (A-side)
__device__ f16  g_k2 [(size_t)BB*SS*512];    // K fp16 (B-side)
__device__ f16  g_v2 [(size_t)BB*CC*1024];   // V transposed [B,C,S] fp16 (B-side)
__device__ f16  g_p2 [(size_t)BB*SS*1024];   // probs [B*S, S] fp16 (A-side)
__device__ f16  g_ao2[(size_t)BB*SS*512];    // attn out fp16 (B-side for proj)
__device__ float g_sc [(size_t)BB*SS*SS];    // scores fp32

// ---------------- helpers ----------------
__device__ __forceinline__ uint32_t smem_u32(const void* p) {
    uint32_t a;
    asm("{ .reg .u64 t; cvta.to.shared.u64 t, %1; cvt.u32.u64 %0, t; }" : "=r"(a) : "l"(p));
    return a;
}
#define CP_ASYNC16(dst, src) \
    asm volatile("cp.async.cg.shared.global [%0], [%1], 16;" :: "r"(dst), "l"(src) : "memory")
#define CP_COMMIT() asm volatile("cp.async.commit_group;" ::: "memory")
#define CP_WAIT0()  asm volatile("cp.async.wait_group 0;" ::: "memory")
#define CP_WAIT1()  asm volatile("cp.async.wait_group 1;" ::: "memory")
#define CP_WAIT2()  asm volatile("cp.async.wait_group 2;" ::: "memory")
#define LDM_X4(r0,r1,r2,r3,addr) \
    asm volatile("ldmatrix.sync.aligned.m8n8.x4.shared.b16 {%0,%1,%2,%3}, [%4];" \
        : "=r"(r0),"=r"(r1),"=r"(r2),"=r"(r3) : "r"(addr))
#define MMA16816(d, a, b0, b1) \
    asm volatile("mma.sync.aligned.m16n8k16.row.col.f32.f16.f16.f32 " \
        "{%0,%1,%2,%3}, {%4,%5,%6,%7}, {%8,%9}, {%0,%1,%2,%3};" \
        : "+f"((d)[0]), "+f"((d)[1]), "+f"((d)[2]), "+f"((d)[3]) \
        : "r"((a)[0]), "r"((a)[1]), "r"((a)[2]), "r"((a)[3]), "r"(b0), "r"(b1))

// ---------------- weight convert (plain fp16) ----------------
__global__ void wconv(const float* __restrict__ w1s, const float* __restrict__ w2s) {
    int i = blockIdx.x * 256 + threadIdx.x;
    if (i < 2048*512) {
        if (i < 1536*512) g_w1[i] = __float2half_rn(w1s[i]);
        else              g_w2[i - 1536*512] = __float2half_rn(w2s[i - 1536*512]);
    }
}

// ---------------- fused GroupNorm stats (partial + last-block finalize) ----------------
__global__ void gn_stats(const float* __restrict__ x) {
    int b = blockIdx.y, chunk = blockIdx.x, t = threadIdx.x;
    const float* p = x + (size_t)b*PER_B + (size_t)chunk*8192;
    float s = 0.f, q = 0.f;
#pragma unroll
    for (int i = 0; i < 32; i++) { float v = p[t + i*256]; s += v; q += v*v; }
    __shared__ float ss_[8], sq_[8];
    for (int o = 16; o > 0; o >>= 1) {
        s += __shfl_down_sync(0xffffffffu, s, o);
        q += __shfl_down_sync(0xffffffffu, q, o);
    }
    if ((t & 31) == 0) { ss_[t >> 5] = s; sq_[t >> 5] = q; }
    __syncthreads();
    __shared__ int isLast;
    if (t == 0) {
        float S2 = 0.f, Q2 = 0.f;
#pragma unroll
        for (int i = 0; i < 8; i++) { S2 += ss_[i]; Q2 += sq_[i]; }
        g_psum[b*64 + chunk] = S2; g_psq[b*64 + chunk] = Q2;
        __threadfence();
        unsigned v = atomicAdd(&g_ctr, 1u);
        isLast = (v == 64u*BB - 1u);
    }
    __syncthreads();
    if (isLast) {
        if (t < BB) {
            float s2 = 0.f, q2 = 0.f;
            for (int i = 0; i < 64; i++) { s2 += g_psum[t*64+i]; q2 += g_psq[t*64+i]; }
            float mean = s2 * (1.f/(float)PER_B);
            float var  = q2 * (1.f/(float)PER_B) - mean*mean;
            g_stats[2*t] = mean; g_stats[2*t+1] = rsqrtf(var + 1e-5f);
        }
        if (t == 0) g_ctr = 0u;
    }
}

// ---------------- normalize + transpose -> g_h2 [B*S, C] fp16 ----------------
__global__ void norm_split(const float* __restrict__ x,
                           const float* __restrict__ gw,
                           const float* __restrict__ gb) {
    __shared__ float tile[32][33];
    int b = blockIdx.z;
    int s0 = blockIdx.x * 32, c0 = blockIdx.y * 32;
    int tx = threadIdx.x, ty = threadIdx.y;
    const float* xp = x + (size_t)b * PER_B;
#pragma unroll
    for (int i = 0; i < 4; i++) {
        int c = c0 + ty + i*8;
        tile[ty + i*8][tx] = xp[(size_t)c*SS + s0 + tx];
    }
    __syncthreads();
    float mean = g_stats[2*b], inv = g_stats[2*b+1];
    int c = c0 + tx;
    float w  = gw[c] * inv;
    float bias = gb[c] - mean * w;
#pragma unroll
    for (int i = 0; i < 4; i++) {
        int s = s0 + ty + i*8;
        float v = tile[tx][ty + i*8] * w + bias;
        g_h2[((size_t)b*SS + s) * 512 + c] = __float2half_rn(v);
    }
}

// ---------------- HMMA GEMM: 128x128 CTA, 8 warps (32x64 each), BK=32, 4-stage ----------------
// NT: out[m,n] = sum_k A[m,k]*B[n,k]
// EPI: 0 = QKV out (Q/K direct, V staged transpose), 1 = scores*scale,
//      2 = AV out, 3 = proj^T: A=w2, out[c,s] direct with bias+resid
#define STAGE_BYTES 20480        // A 128x80 (10240) + B 128x80 (10240)
#define DYN_SMEM 81920           // 4 stages; V-staging (67584) fits inside

__device__ __forceinline__ void prefetch_tile(char* smem, int stage,
    const f16* __restrict__ A, int lda, const f16* __restrict__ B, int ldb,
    int m0, int n0, int k0, int tid)
{
    char* as = smem + stage*STAGE_BYTES;
    char* bs = as + 10240;
    int row = tid >> 1, seg = tid & 1;
    const f16* ag = A + (size_t)(m0 + row)*lda + k0 + seg*16;
    const f16* bg = B + (size_t)(n0 + row)*ldb + k0 + seg*16;
    uint32_t asw = smem_u32(as + row*80 + seg*32);
    uint32_t bsw = smem_u32(bs + row*80 + seg*32);
    CP_ASYNC16(asw,      (const void*)ag);
    CP_ASYNC16(asw + 16, (const void*)(ag + 8));
    CP_ASYNC16(bsw,      (const void*)bg);
    CP_ASYNC16(bsw + 16, (const void*)(bg + 8));
}

template<int EPI>
__global__ __launch_bounds__(256, 2)
void mm_gemm(const f16* __restrict__ A, int lda, long long sA,
             const f16* __restrict__ B, int ldb, long long sB,
             float* __restrict__ Out,
             const float* __restrict__ bias,
             const float* __restrict__ resid,
             float scale, int K)
{
    extern __shared__ char smem[];
    int tid = threadIdx.x, lane = tid & 31, wid = tid >> 5;
    int wm = wid >> 1, wn = wid & 1;          // 4 x 2 warp grid, 32x64 tiles
    int z = blockIdx.z;
    int m0 = blockIdx.y * 128, n0 = blockIdx.x * 128;
    A += (size_t)z * sA;
    B += (size_t)z * sB;

    float acc[2][8][4];
#pragma unroll
    for (int i = 0; i < 2; i++)
#pragma unroll
        for (int j = 0; j < 8; j++)
#pragma unroll
            for (int r = 0; r < 4; r++) acc[i][j][r] = 0.f;

    uint32_t a_off = (uint32_t)((wm*32 + (lane & 15)) * 80 + (lane >> 4) * 16);
    uint32_t b_off = (uint32_t)((wn*64 + (lane & 7) + ((lane >> 4) << 3)) * 80
                                + ((lane >> 3) & 1) * 16);
    uint32_t smem_base = smem_u32(smem);

    int nch = K >> 5;
#pragma unroll
    for (int p = 0; p < 3; p++) {
        if (p < nch) { prefetch_tile(smem, p, A, lda, B, ldb, m0, n0, p*32, tid); CP_COMMIT(); }
    }

    int st = 0;
    for (int c = 0; c < nch; c++) {
        int rem = nch - 1 - c;
        if (rem >= 2) CP_WAIT2(); else if (rem == 1) CP_WAIT1(); else CP_WAIT0();
        __syncthreads();
        if (c + 3 < nch) {
            prefetch_tile(smem, (st + 3) & 3, A, lda, B, ldb, m0, n0, (c+3)*32, tid);
            CP_COMMIT();
        }

        uint32_t as_b = smem_base + st*STAGE_BYTES + a_off;
        uint32_t bs_b = smem_base + st*STAGE_BYTES + 10240 + b_off;
#pragma unroll
        for (int ks = 0; ks < 2; ks++) {
            uint32_t a[2][4], b[4][4];
#pragma unroll
            for (int mf = 0; mf < 2; mf++)
                LDM_X4(a[mf][0], a[mf][1], a[mf][2], a[mf][3], as_b + mf*1280 + ks*32);
#pragma unroll
            for (int nf2 = 0; nf2 < 4; nf2++)
                LDM_X4(b[nf2][0], b[nf2][1], b[nf2][2], b[nf2][3], bs_b + nf2*1280 + ks*32);
#pragma unroll
            for (int mf = 0; mf < 2; mf++)
#pragma unroll
                for (int nf = 0; nf < 8; nf++)
                    MMA16816(acc[mf][nf], a[mf], b[nf>>1][(nf&1)*2], b[nf>>1][(nf&1)*2+1]);
        }
        st = (st + 1) & 3;
    }

    int r4 = lane >> 2, cp = (lane & 3) * 2;

    if constexpr (EPI == 0) {
        if (n0 < 1024) {             // Q / K direct half2 stores
            f16* dst = (n0 < 512) ? g_q2 : g_k2;
            int nbase = (n0 < 512) ? n0 : (n0 - 512);
#pragma unroll
            for (int mf = 0; mf < 2; mf++)
#pragma unroll
                for (int nf = 0; nf < 8; nf++) {
                    int rr = m0 + wm*32 + mf*16 + r4;
                    int cc = wn*64 + nf*8 + cp;
                    float b0 = bias[n0 + cc], b1 = bias[n0 + cc + 1];
                    *(__half2*)&dst[(size_t)rr * 512 + nbase + cc] =
                        __floats2half2_rn(acc[mf][nf][0] + b0, acc[mf][nf][1] + b1);
                    *(__half2*)&dst[(size_t)(rr + 8) * 512 + nbase + cc] =
                        __floats2half2_rn(acc[mf][nf][2] + b0, acc[mf][nf][3] + b1);
                }
        } else {                     // V: staged transpose -> [B,C,S]
            __syncthreads();
            float* tile = (float*)smem;
#pragma unroll
            for (int mf = 0; mf < 2; mf++)
#pragma unroll
                for (int nf = 0; nf < 8; nf++) {
                    int rr = wm*32 + mf*16 + r4, cc = wn*64 + nf*8 + cp;
                    tile[rr*132 + cc]       = acc[mf][nf][0];
                    tile[rr*132 + cc + 1]   = acc[mf][nf][1];
                    tile[(rr+8)*132 + cc]   = acc[mf][nf][2];
                    tile[(rr+8)*132 + cc+1] = acc[mf][nf][3];
                }
            __syncthreads();
            for (int idx = tid; idx < 16384; idx += 256) {
                int rt = idx & 127, ct = idx >> 7;
                float v = tile[rt*132 + ct] + bias[n0 + ct];
                int m = m0 + rt, b = m >> 10, s = m & 1023;
                int cg = n0 + ct - 1024;
                g_v2[((size_t)b*512 + cg) * 1024 + s] = __float2half_rn(v);
            }
        }
    } else if constexpr (EPI == 1) { // scores fp32 direct float2
        float* op = Out + (size_t)z * SS * SS;
#pragma unroll
        for (int mf = 0; mf < 2; mf++)
#pragma unroll
            for (int nf = 0; nf < 8; nf++) {
                int rr = m0 + wm*32 + mf*16 + r4;
                int cc = n0 + wn*64 + nf*8 + cp;
                float2 v0 = {acc[mf][nf][0] * scale, acc[mf][nf][1] * scale};
                float2 v1 = {acc[mf][nf][2] * scale, acc[mf][nf][3] * scale};
                *(float2*)&op[(size_t)rr * SS + cc] = v0;
                *(float2*)&op[(size_t)(rr + 8) * SS + cc] = v1;
            }
    } else if constexpr (EPI == 2) { // AV direct half2
#pragma unroll
        for (int mf = 0; mf < 2; mf++)
#pragma unroll
            for (int nf = 0; nf < 8; nf++) {
                int rr = m0 + wm*32 + mf*16 + r4;
                int cc = n0 + wn*64 + nf*8 + cp;
                *(__half2*)&g_ao2[((size_t)z * SS + rr) * 512 + cc] =
                    __floats2half2_rn(acc[mf][nf][0], acc[mf][nf][1]);
                *(__half2*)&g_ao2[((size_t)z * SS + rr + 8) * 512 + cc] =
                    __floats2half2_rn(acc[mf][nf][2], acc[mf][nf][3]);
            }
    } else {                         // proj^T: m=c-dim, n=global s; direct float2 + bias + resid
#pragma unroll
        for (int mf = 0; mf < 2; mf++) {
            int rr = m0 + wm*32 + mf*16 + r4;
            float bias_r  = bias[rr], bias_r8 = bias[rr + 8];
#pragma unroll
            for (int nf = 0; nf < 8; nf++) {
                int n = n0 + wn*64 + nf*8 + cp;
                int b = n >> 10, s = n & 1023;
                size_t o0 = ((size_t)b * 512 + rr) * 1024 + s;
                size_t o1 = ((size_t)b * 512 + rr + 8) * 1024 + s;
                float2 rv0 = *(const float2*)&resid[o0];
                float2 rv1 = *(const float2*)&resid[o1];
                float2 w0 = {acc[mf][nf][0] + bias_r  + rv0.x, acc[mf][nf][1] + bias_r  + rv0.y};
                float2 w1 = {acc[mf][nf][2] + bias_r8 + rv1.x, acc[mf][nf][3] + bias_r8 + rv1.y};
                *(float2*)&Out[o0] = w0;
                *(float2*)&Out[o1] = w1;
            }
        }
    }
}

// ---------------- softmax over 1024-wide rows, plain fp16 output ----------------
__global__ void softmax_rows(const float* __restrict__ sc) {
    const float* row = sc + (size_t)blockIdx.x * SS;
    f16* orow = g_p2 + (size_t)blockIdx.x * 1024;
    int t = threadIdx.x;
    float v[4];
#pragma unroll
    for (int i = 0; i < 4; i++) v[i] = row[t + i*256];
    float m = fmaxf(fmaxf(v[0], v[1]), fmaxf(v[2], v[3]));
    __shared__ float red[8];
    for (int o = 16; o > 0; o >>= 1) m = fmaxf(m, __shfl_xor_sync(0xffffffffu, m, o));
    if ((t & 31) == 0) red[t >> 5] = m;
    __syncthreads();
    float mm = fmaxf(fmaxf(fmaxf(red[0], red[1]), fmaxf(red[2], red[3])),
                     fmaxf(fmaxf(red[4], red[5]), fmaxf(red[6], red[7])));
    float s = 0.f;
#pragma unroll
    for (int i = 0; i < 4; i++) { v[i] = __expf(v[i] - mm); s += v[i]; }
    for (int o = 16; o > 0; o >>= 1) s += __shfl_xor_sync(0xffffffffu, s, o);
    __syncthreads();
    if ((t & 31) == 0) red[t >> 5] = s;
    __syncthreads();
    float tot = ((red[0]+red[1]) + (red[2]+red[3])) + ((red[4]+red[5]) + (red[6]+red[7]));
    float invs = 1.f / tot;
#pragma unroll
    for (int i = 0; i < 4; i++)
        orow[t + i*256] = __float2half_rn(v[i] * invs);
}

// ---------------- launch ----------------
extern "C" void kernel_launch(void* const* d_in, const int* in_sizes, int n_in,
                              void* d_out, int out_size) {
    const float* x      = (const float*)d_in[0];
    const float* gn_w   = (const float*)d_in[1];
    const float* gn_b   = (const float*)d_in[2];
    const float* qkv_w  = (const float*)d_in[3];
    const float* qkv_b  = (const float*)d_in[4];
    const float* proj_w = (const float*)d_in[5];
    const float* proj_b = (const float*)d_in[6];
    float* out = (float*)d_out;

    cudaFuncSetAttribute(mm_gemm<0>, cudaFuncAttributeMaxDynamicSharedMemorySize, DYN_SMEM);
    cudaFuncSetAttribute(mm_gemm<1>, cudaFuncAttributeMaxDynamicSharedMemorySize, DYN_SMEM);
    cudaFuncSetAttribute(mm_gemm<2>, cudaFuncAttributeMaxDynamicSharedMemorySize, DYN_SMEM);
    cudaFuncSetAttribute(mm_gemm<3>, cudaFuncAttributeMaxDynamicSharedMemorySize, DYN_SMEM);

    f16 *h2, *w1, *w2, *q2, *k2, *v2, *p2, *ao2; float* sc;
    cudaGetSymbolAddress((void**)&h2,  g_h2);
    cudaGetSymbolAddress((void**)&w1,  g_w1);
    cudaGetSymbolAddress((void**)&w2,  g_w2);
    cudaGetSymbolAddress((void**)&q2,  g_q2);
    cudaGetSymbolAddress((void**)&k2,  g_k2);
    cudaGetSymbolAddress((void**)&v2,  g_v2);
    cudaGetSymbolAddress((void**)&p2,  g_p2);
    cudaGetSymbolAddress((void**)&ao2, g_ao2);
    cudaGetSymbolAddress((void**)&sc,  g_sc);

    // 1. weight convert
    wconv<<<(2048*512 + 255)/256, 256>>>(qkv_w, proj_w);

    // 2. fused GroupNorm stats
    gn_stats<<<dim3(64, BB), 256>>>(x);

    // 3. normalize + transpose (fp16)
    norm_split<<<dim3(SS/32, CC/32, BB), dim3(32, 8)>>>(x, gn_w, gn_b);

    // 4. QKV GEMM: M=16384, N=1536, K=512
    mm_gemm<0><<<dim3(12, 128, 1), 256, DYN_SMEM>>>(
        h2, 512, 0LL, w1, 512, 0LL,
        nullptr, qkv_b, nullptr, 1.f, 512);

    // 5. scores = scale * Q K^T, batched: K=512
    mm_gemm<1><<<dim3(8, 8, BB), 256, DYN_SMEM>>>(
        q2, 512, 1024LL*512, k2, 512, 1024LL*512, sc,
        nullptr, nullptr, 0.044194173824159216f, 512);

    // 6. softmax
    softmax_rows<<<BB*SS, 256>>>(sc);

    // 7. attn @ V: M=1024, N=512, K=1024, batched
    mm_gemm<2><<<dim3(4, 8, BB), 256, DYN_SMEM>>>(
        p2, 1024, 1024LL*1024, v2, 1024, 512LL*1024, nullptr,
        nullptr, nullptr, 1.f, 1024);

    // 8. proj^T + bias + residual -> NCHW out: M=512 (c), N=16384 (b*s), K=512
    mm_gemm<3><<<dim3(128, 4, 1), 256, DYN_SMEM>>>(
        w2, 512, 0LL, ao2, 512, 0LL, out, proj_b, x, 1.f, 512);
}